// round 1
// baseline (speedup 1.0000x reference)
#include <cuda_runtime.h>
#include <cstdint>

// Problem constants
#define BSZ   4096          // batch (GEMM M)
#define DK    2048          // in_features (GEMM K)
#define NCOMP 8
#define CCH   1024
#define NOUT  (NCOMP*CCH)   // 8192 (GEMM N)

// GEMM tiling
#define BM 128
#define BN 128
#define BK 32
#define LDS_A 36            // padded float stride (144B, 16B aligned, conflict-free)
#define LDS_B 36
#define GEMM_THREADS 256
#define SMEM_BYTES (2*(BM*LDS_A + BN*LDS_B)*4)   // 73728

// Scratch: tf32-pre-rounded operands + gate results (static device arrays, no allocs)
__device__ float d_xr[(size_t)BSZ * DK];     // 32 MB
__device__ float d_wr[(size_t)NOUT * DK];    // 64 MB
__device__ float d_ginv[BSZ];
__device__ int   d_gk[BSZ];

// ---------------------------------------------------------------------------
// helpers
// ---------------------------------------------------------------------------
__device__ __forceinline__ float ftf32(float f) {
    uint32_t u;
    asm("cvt.rna.tf32.f32 %0, %1;" : "=r"(u) : "f"(f));
    return __uint_as_float(u);
}

__device__ __forceinline__ void cpa16(void* dst_smem, const void* src_gmem) {
    uint32_t d = (uint32_t)__cvta_generic_to_shared(dst_smem);
    asm volatile("cp.async.cg.shared.global [%0], [%1], 16;\n" :: "r"(d), "l"(src_gmem));
}

// ---------------------------------------------------------------------------
// 1) round x, W to tf32 (round-to-nearest) into scratch
// ---------------------------------------------------------------------------
__global__ void round_x_kernel(const float* __restrict__ x) {
    size_t i = (size_t)blockIdx.x * blockDim.x + threadIdx.x;   // in float4 units
    float4 v = reinterpret_cast<const float4*>(x)[i];
    v.x = ftf32(v.x); v.y = ftf32(v.y); v.z = ftf32(v.z); v.w = ftf32(v.w);
    reinterpret_cast<float4*>(d_xr)[i] = v;
}

__global__ void round_w_kernel(const float* __restrict__ w) {
    size_t i = (size_t)blockIdx.x * blockDim.x + threadIdx.x;
    float4 v = reinterpret_cast<const float4*>(w)[i];
    v.x = ftf32(v.x); v.y = ftf32(v.y); v.z = ftf32(v.z); v.w = ftf32(v.w);
    reinterpret_cast<float4*>(d_wr)[i] = v;
}

// ---------------------------------------------------------------------------
// 2) gate: one warp per sample. g = 4*(1+tanh(x.wg + bg)); k=floor(g);
//    G[b,n] = (n<=k) ? 1/min(k+1,8) : 0
// ---------------------------------------------------------------------------
__global__ void gate_kernel(const float* __restrict__ x,
                            const float* __restrict__ wg,
                            const float* __restrict__ wgb,
                            float* __restrict__ Gout) {
    int warp = (blockIdx.x * blockDim.x + threadIdx.x) >> 5;
    int lane = threadIdx.x & 31;
    if (warp >= BSZ) return;
    const float* xr = x + (size_t)warp * DK;
    float s = 0.f;
    #pragma unroll 8
    for (int i = lane; i < DK; i += 32) s = fmaf(xr[i], wg[i], s);
    #pragma unroll
    for (int o = 16; o; o >>= 1) s += __shfl_xor_sync(0xffffffffu, s, o);
    float g = 4.0f * (1.0f + tanhf(s + wgb[0]));
    int k = (int)floorf(g);
    if (k < 0) k = 0;
    int cnt = k + 1; if (cnt > NCOMP) cnt = NCOMP;
    float inv = 1.0f / (float)cnt;
    if (lane == 0) { d_ginv[warp] = inv; d_gk[warp] = k; }
    if (Gout != nullptr && lane < NCOMP)
        Gout[(size_t)warp * NCOMP + lane] = (lane <= k) ? inv : 0.0f;
}

// ---------------------------------------------------------------------------
// 3) GEMM: out[b,j] = (n<=k[b]) ? (x[b,:].W[j,:] + bias[j]) * inv[b] : 0
//    tf32 mma.sync m16n8k8, 128x128x32 tiles, 2-stage cp.async pipeline
// ---------------------------------------------------------------------------
__global__ __launch_bounds__(GEMM_THREADS, 2)
void gemm_kernel(const float* __restrict__ bias, float* __restrict__ out) {
    extern __shared__ float smem[];
    float* As = smem;                      // [2][BM][LDS_A]
    float* Bs = smem + 2 * BM * LDS_A;     // [2][BN][LDS_B]

    const int tid  = threadIdx.x;
    const int lane = tid & 31;
    const int warp = tid >> 5;
    const int wm   = warp >> 2;            // 0..1  (64 rows each)
    const int wn   = warp & 3;             // 0..3  (32 cols each)
    const int rowBase = blockIdx.y * BM;
    const int colBase = blockIdx.x * BN;
    const int lr = lane >> 2;              // 0..7
    const int lc = lane & 3;               // 0..3

    float c[4][4][4];
    #pragma unroll
    for (int i = 0; i < 4; i++)
        #pragma unroll
        for (int j = 0; j < 4; j++)
            #pragma unroll
            for (int r = 0; r < 4; r++) c[i][j][r] = 0.f;

    auto loadStage = [&](int s, int kt) {
        const int k0 = kt * BK;
        #pragma unroll
        for (int i = 0; i < 4; i++) {
            int idx = tid + i * GEMM_THREADS;   // 0..1023
            int r  = idx >> 3;                  // 0..127
            int ch = idx & 7;                   // 0..7 (16B chunks)
            cpa16(&As[(size_t)s * BM * LDS_A + r * LDS_A + ch * 4],
                  d_xr + (size_t)(rowBase + r) * DK + k0 + ch * 4);
            cpa16(&Bs[(size_t)s * BN * LDS_B + r * LDS_B + ch * 4],
                  d_wr + (size_t)(colBase + r) * DK + k0 + ch * 4);
        }
        asm volatile("cp.async.commit_group;\n" ::);
    };

    auto computeStage = [&](int s) {
        const float* as = &As[(size_t)s * BM * LDS_A];
        const float* bs = &Bs[(size_t)s * BN * LDS_B];
        #pragma unroll
        for (int ks = 0; ks < BK / 8; ks++) {
            const int kc = ks * 8 + lc;
            uint32_t a[4][4], b[4][2];
            #pragma unroll
            for (int i = 0; i < 4; i++) {
                int r0 = wm * 64 + i * 16;
                a[i][0] = __float_as_uint(as[(r0 + lr)     * LDS_A + kc]);
                a[i][1] = __float_as_uint(as[(r0 + lr + 8) * LDS_A + kc]);
                a[i][2] = __float_as_uint(as[(r0 + lr)     * LDS_A + kc + 4]);
                a[i][3] = __float_as_uint(as[(r0 + lr + 8) * LDS_A + kc + 4]);
            }
            #pragma unroll
            for (int j = 0; j < 4; j++) {
                int n0 = wn * 32 + j * 8;
                b[j][0] = __float_as_uint(bs[(n0 + lr) * LDS_B + kc]);
                b[j][1] = __float_as_uint(bs[(n0 + lr) * LDS_B + kc + 4]);
            }
            #pragma unroll
            for (int i = 0; i < 4; i++)
                #pragma unroll
                for (int j = 0; j < 4; j++)
                    asm volatile(
                        "mma.sync.aligned.m16n8k8.row.col.f32.tf32.tf32.f32 "
                        "{%0,%1,%2,%3},{%4,%5,%6,%7},{%8,%9},{%0,%1,%2,%3};\n"
                        : "+f"(c[i][j][0]), "+f"(c[i][j][1]),
                          "+f"(c[i][j][2]), "+f"(c[i][j][3])
                        : "r"(a[i][0]), "r"(a[i][1]), "r"(a[i][2]), "r"(a[i][3]),
                          "r"(b[j][0]), "r"(b[j][1]));
        }
    };

    const int KT = DK / BK;   // 64
    loadStage(0, 0);
    #pragma unroll 1
    for (int kt = 0; kt < KT; kt++) {
        const int cur = kt & 1;
        if (kt + 1 < KT) {
            loadStage(cur ^ 1, kt + 1);
            asm volatile("cp.async.wait_group 1;\n" ::);
        } else {
            asm volatile("cp.async.wait_group 0;\n" ::);
        }
        __syncthreads();
        computeStage(cur);
        __syncthreads();
    }

    // epilogue: bias + gate scale / zero
    #pragma unroll
    for (int i = 0; i < 4; i++) {
        const int rTop = rowBase + wm * 64 + i * 16 + lr;
        #pragma unroll
        for (int h = 0; h < 2; h++) {
            const int r = rTop + h * 8;
            const float inv = d_ginv[r];
            const int   kk  = d_gk[r];
            #pragma unroll
            for (int j = 0; j < 4; j++) {
                const int cb = colBase + wn * 32 + j * 8 + lc * 2;
                const int n  = cb >> 10;                    // component index
                const float sc = (n <= kk) ? inv : 0.0f;
                float2 v;
                v.x = (c[i][j][2 * h + 0] + bias[cb])     * sc;
                v.y = (c[i][j][2 * h + 1] + bias[cb + 1]) * sc;
                *reinterpret_cast<float2*>(&out[(size_t)r * NOUT + cb]) = v;
            }
        }
    }
}

// ---------------------------------------------------------------------------
extern "C" void kernel_launch(void* const* d_in, const int* in_sizes, int n_in,
                              void* d_out, int out_size) {
    const float* x    = (const float*)d_in[0];
    const float* W    = (const float*)d_in[1];
    const float* bias = (const float*)d_in[2];
    const float* wg   = (const float*)d_in[3];
    const float* wgb  = (const float*)d_in[4];
    float* out = (float*)d_out;

    // output layout: E [BSZ*NOUT] then G [BSZ*NCOMP] (tuple flattened in order)
    float* Gout = nullptr;
    if ((size_t)out_size >= (size_t)BSZ * NOUT + (size_t)BSZ * NCOMP)
        Gout = out + (size_t)BSZ * NOUT;

    cudaFuncSetAttribute(gemm_kernel, cudaFuncAttributeMaxDynamicSharedMemorySize,
                         SMEM_BYTES);

    // 1) tf32 pre-rounding (round-to-nearest -> unbiased mma inputs)
    round_x_kernel<<<(BSZ * (DK / 4)) / 256, 256>>>(x);
    round_w_kernel<<<((size_t)NOUT * (DK / 4)) / 256, 256>>>(W);

    // 2) gate (1 warp / sample)
    gate_kernel<<<(BSZ * 32) / 256, 256>>>(x, wg, wgb, Gout);

    // 3) fused GEMM + bias + gated scale
    dim3 grid(NOUT / BN, BSZ / BM);   // 64 x 32
    gemm_kernel<<<grid, GEMM_THREADS, SMEM_BYTES>>>(bias, out);
}

// round 3
// speedup vs baseline: 1.0057x; 1.0057x over previous
#include <cuda_runtime.h>
#include <cstdint>

// ---------------------------------------------------------------------------
// Problem constants
// ---------------------------------------------------------------------------
#define BSZ   4096          // batch (GEMM M)
#define DK    2048          // in_features (GEMM K)
#define NCOMP 8
#define NOUT  8192          // GEMM N

// ---------------------------------------------------------------------------
// GEMM tiling: CTA 128x256, warp tile 64x64 (2x4 warp grid), BK=32, 3 stages
// ---------------------------------------------------------------------------
#define BM 128
#define BN 256
#define BK 32
#define KT (DK / BK)              // 64
#define NSTAGE 3
#define LDSD 36                   // padded float stride (144B, 16B-aligned)
#define A_FLOATS (BM * LDSD)      // 4608
#define B_FLOATS (BN * LDSD)      // 9216
#define STAGE_FLOATS (A_FLOATS + B_FLOATS)          // 13824
#define SMEM_BYTES (NSTAGE * STAGE_FLOATS * 4)      // 165888
#define GEMM_THREADS 256

// ---------------------------------------------------------------------------
// Scratch (static device arrays; no allocations)
// ---------------------------------------------------------------------------
__device__ __align__(1024) float d_xr[(size_t)BSZ * DK];     // 32 MB tf32-rounded x
__device__ __align__(1024) float d_wr[(size_t)NOUT * DK];    // 64 MB tf32-rounded W
__device__ float d_ginv[BSZ];
__device__ int   d_gk[BSZ];

// ---------------------------------------------------------------------------
// helpers
// ---------------------------------------------------------------------------
__device__ __forceinline__ float ftf32(float f) {
    uint32_t u;
    asm("cvt.rna.tf32.f32 %0, %1;" : "=r"(u) : "f"(f));
    return __uint_as_float(u);
}

__device__ __forceinline__ void cpa16(void* dst_smem, const void* src_gmem) {
    uint32_t d = (uint32_t)__cvta_generic_to_shared(dst_smem);
    asm volatile("cp.async.cg.shared.global [%0], [%1], 16;\n" :: "r"(d), "l"(src_gmem));
}

// ---------------------------------------------------------------------------
// 1) tf32 pre-rounding (round-to-nearest, unbiased)
// ---------------------------------------------------------------------------
__global__ void round_x_kernel(const float* __restrict__ x) {
    size_t i = (size_t)blockIdx.x * blockDim.x + threadIdx.x;
    float4 v = reinterpret_cast<const float4*>(x)[i];
    v.x = ftf32(v.x); v.y = ftf32(v.y); v.z = ftf32(v.z); v.w = ftf32(v.w);
    reinterpret_cast<float4*>(d_xr)[i] = v;
}
__global__ void round_w_kernel(const float* __restrict__ w) {
    size_t i = (size_t)blockIdx.x * blockDim.x + threadIdx.x;
    float4 v = reinterpret_cast<const float4*>(w)[i];
    v.x = ftf32(v.x); v.y = ftf32(v.y); v.z = ftf32(v.z); v.w = ftf32(v.w);
    reinterpret_cast<float4*>(d_wr)[i] = v;
}

// ---------------------------------------------------------------------------
// 2) gate: one warp per sample
// ---------------------------------------------------------------------------
__global__ void gate_kernel(const float* __restrict__ x,
                            const float* __restrict__ wg,
                            const float* __restrict__ wgb,
                            float* __restrict__ Gout) {
    int warp = (blockIdx.x * blockDim.x + threadIdx.x) >> 5;
    int lane = threadIdx.x & 31;
    if (warp >= BSZ) return;
    const float* xr = x + (size_t)warp * DK;
    float s = 0.f;
    #pragma unroll 8
    for (int i = lane; i < DK; i += 32) s = fmaf(xr[i], wg[i], s);
    #pragma unroll
    for (int o = 16; o; o >>= 1) s += __shfl_xor_sync(0xffffffffu, s, o);
    float g = 4.0f * (1.0f + tanhf(s + wgb[0]));
    int k = (int)floorf(g);
    if (k < 0) k = 0;
    int cnt = k + 1; if (cnt > NCOMP) cnt = NCOMP;
    float inv = 1.0f / (float)cnt;
    if (lane == 0) { d_ginv[warp] = inv; d_gk[warp] = k; }
    if (Gout != nullptr && lane < NCOMP)
        Gout[(size_t)warp * NCOMP + lane] = (lane <= k) ? inv : 0.0f;
}

// ---------------------------------------------------------------------------
// 3) GEMM: out[b,j] = (n<=k[b]) ? (x[b,:].W[j,:] + bias[j]) * inv[b] : 0
//    tf32 mma.sync m16n8k8, CTA 128x256, warp 64x64, 3-stage cp.async
// ---------------------------------------------------------------------------
__global__ __launch_bounds__(GEMM_THREADS, 1)
void gemm_kernel(const float* __restrict__ bias, float* __restrict__ out) {
    extern __shared__ float smem[];

    const int tid  = threadIdx.x;
    const int lane = tid & 31;
    const int warp = tid >> 5;
    const int wm   = warp >> 2;            // 0..1  (64 rows each)
    const int wn   = warp & 3;             // 0..3  (64 cols each)
    const int rowBase = blockIdx.y * BM;
    const int colBase = blockIdx.x * BN;
    const int lr = lane >> 2;              // 0..7
    const int lc = lane & 3;               // 0..3

    float c[4][8][4];
    #pragma unroll
    for (int i = 0; i < 4; i++)
        #pragma unroll
        for (int j = 0; j < 8; j++)
            #pragma unroll
            for (int r = 0; r < 4; r++) c[i][j][r] = 0.f;

    auto loadStage = [&](int s, int kt) {
        const int k0 = kt * BK;
        float* As = smem + (size_t)s * STAGE_FLOATS;
        float* Bs = As + A_FLOATS;
        // A: 128 rows x 8 chunks = 1024 chunks, 4 per thread
        #pragma unroll
        for (int i = 0; i < 4; i++) {
            int idx = tid + i * GEMM_THREADS;
            int r  = idx >> 3;
            int ch = idx & 7;
            cpa16(&As[r * LDSD + ch * 4],
                  d_xr + (size_t)(rowBase + r) * DK + k0 + ch * 4);
        }
        // B: 256 rows x 8 chunks = 2048 chunks, 8 per thread
        #pragma unroll
        for (int i = 0; i < 8; i++) {
            int idx = tid + i * GEMM_THREADS;
            int r  = idx >> 3;
            int ch = idx & 7;
            cpa16(&Bs[r * LDSD + ch * 4],
                  d_wr + (size_t)(colBase + r) * DK + k0 + ch * 4);
        }
        asm volatile("cp.async.commit_group;\n" ::);
    };

    auto computeStage = [&](int s) {
        const float* as = smem + (size_t)s * STAGE_FLOATS;
        const float* bs = as + A_FLOATS;
        #pragma unroll
        for (int ks = 0; ks < BK / 8; ks++) {
            const int kc = ks * 8 + lc;
            uint32_t a[4][4], b[8][2];
            #pragma unroll
            for (int i = 0; i < 4; i++) {
                int r0 = wm * 64 + i * 16;
                a[i][0] = __float_as_uint(as[(r0 + lr)     * LDSD + kc]);
                a[i][1] = __float_as_uint(as[(r0 + lr + 8) * LDSD + kc]);
                a[i][2] = __float_as_uint(as[(r0 + lr)     * LDSD + kc + 4]);
                a[i][3] = __float_as_uint(as[(r0 + lr + 8) * LDSD + kc + 4]);
            }
            #pragma unroll
            for (int j = 0; j < 8; j++) {
                int n0 = wn * 64 + j * 8;
                b[j][0] = __float_as_uint(bs[(n0 + lr) * LDSD + kc]);
                b[j][1] = __float_as_uint(bs[(n0 + lr) * LDSD + kc + 4]);
            }
            #pragma unroll
            for (int i = 0; i < 4; i++)
                #pragma unroll
                for (int j = 0; j < 8; j++)
                    asm volatile(
                        "mma.sync.aligned.m16n8k8.row.col.f32.tf32.tf32.f32 "
                        "{%0,%1,%2,%3},{%4,%5,%6,%7},{%8,%9},{%0,%1,%2,%3};\n"
                        : "+f"(c[i][j][0]), "+f"(c[i][j][1]),
                          "+f"(c[i][j][2]), "+f"(c[i][j][3])
                        : "r"(a[i][0]), "r"(a[i][1]), "r"(a[i][2]), "r"(a[i][3]),
                          "r"(b[j][0]), "r"(b[j][1]));
        }
    };

    // prefetch stages 0..NSTAGE-2
    loadStage(0, 0);
    loadStage(1, 1);

    #pragma unroll 1
    for (int kt = 0; kt < KT; kt++) {
        asm volatile("cp.async.wait_group %0;\n" :: "n"(NSTAGE - 2));
        __syncthreads();
        // refill the buffer consumed at iteration kt-1 (safe after the sync)
        if (kt + NSTAGE - 1 < KT)
            loadStage((kt + NSTAGE - 1) % NSTAGE, kt + NSTAGE - 1);
        computeStage(kt % NSTAGE);
    }

    // ---------------- epilogue: bias + gated scale ----------------
    float invs[4][2]; int kks[4][2];
    #pragma unroll
    for (int i = 0; i < 4; i++)
        #pragma unroll
        for (int h = 0; h < 2; h++) {
            int r = rowBase + wm * 64 + i * 16 + lr + h * 8;
            invs[i][h] = d_ginv[r];
            kks[i][h]  = d_gk[r];
        }
    // component index is constant across a warp's 64-col span
    const int comp = (colBase + wn * 64) >> 10;

    #pragma unroll
    for (int i = 0; i < 4; i++) {
        #pragma unroll
        for (int h = 0; h < 2; h++) {
            const int r = rowBase + wm * 64 + i * 16 + lr + h * 8;
            const float sc = (comp <= kks[i][h]) ? invs[i][h] : 0.0f;
            #pragma unroll
            for (int j = 0; j < 8; j++) {
                const int cb = colBase + wn * 64 + j * 8 + lc * 2;
                const float2 bb = *reinterpret_cast<const float2*>(&bias[cb]);
                float2 v;
                v.x = (c[i][j][2 * h + 0] + bb.x) * sc;
                v.y = (c[i][j][2 * h + 1] + bb.y) * sc;
                *reinterpret_cast<float2*>(&out[(size_t)r * NOUT + cb]) = v;
            }
        }
    }
}

// ---------------------------------------------------------------------------
extern "C" void kernel_launch(void* const* d_in, const int* in_sizes, int n_in,
                              void* d_out, int out_size) {
    const float* x    = (const float*)d_in[0];
    const float* W    = (const float*)d_in[1];
    const float* bias = (const float*)d_in[2];
    const float* wg   = (const float*)d_in[3];
    const float* wgb  = (const float*)d_in[4];
    float* out = (float*)d_out;

    // output layout: E [BSZ*NOUT] then G [BSZ*NCOMP]
    float* Gout = nullptr;
    if ((size_t)out_size >= (size_t)BSZ * NOUT + (size_t)BSZ * NCOMP)
        Gout = out + (size_t)BSZ * NOUT;

    cudaFuncSetAttribute(gemm_kernel, cudaFuncAttributeMaxDynamicSharedMemorySize,
                         SMEM_BYTES);

    // 1) tf32 pre-rounding
    round_x_kernel<<<(BSZ * (DK / 4)) / 256, 256>>>(x);
    round_w_kernel<<<((size_t)NOUT * (DK / 4)) / 256, 256>>>(W);

    // 2) gate (1 warp / sample)
    gate_kernel<<<(BSZ * 32) / 256, 256>>>(x, wg, wgb, Gout);

    // 3) fused GEMM + bias + gated scale
    dim3 grid(NOUT / BN, BSZ / BM);   // 32 x 32
    gemm_kernel<<<grid, GEMM_THREADS, SMEM_BYTES>>>(bias, out);
}

// round 4
// speedup vs baseline: 1.5643x; 1.5554x over previous
#include <cuda_runtime.h>
#include <cstdint>

// ---------------------------------------------------------------------------
// Problem constants
// ---------------------------------------------------------------------------
#define BSZ   4096          // batch (GEMM M)
#define DK    2048          // in_features (GEMM K)
#define NCOMP 8
#define CCH   1024
#define NOUT  8192          // GEMM N

// ---------------------------------------------------------------------------
// GEMM tiling: CTA 128x256, warp tile 64x64 (2x4 warp grid), BK=32, 3 stages
// ---------------------------------------------------------------------------
#define BM 128
#define BN 256
#define BK 32
#define KT (DK / BK)              // 64
#define NSTAGE 3
#define LDSD 36                   // padded float stride (144B, 16B-aligned)
#define A_FLOATS (BM * LDSD)      // 4608
#define B_FLOATS (BN * LDSD)      // 9216
#define STAGE_FLOATS (A_FLOATS + B_FLOATS)          // 13824
#define SPERM_BYTES 512
#define SMEM_BYTES (SPERM_BYTES + NSTAGE * STAGE_FLOATS * 4)   // 166400
#define GEMM_THREADS 256

// ---------------------------------------------------------------------------
// Scratch (static device arrays; no allocations)
// ---------------------------------------------------------------------------
__device__ __align__(1024) float d_xr[(size_t)BSZ * DK];     // 32 MB tf32-rounded x
__device__ __align__(1024) float d_wr[(size_t)NOUT * DK];    // 64 MB tf32-rounded W
__device__ float d_ginv[BSZ];
__device__ int   d_gk[BSZ];
__device__ int   d_perm[BSZ];        // rows sorted by k descending
__device__ int   d_cnt_ge[NCOMP + 1];// cnt_ge[n] = #rows with k >= n

// ---------------------------------------------------------------------------
// helpers
// ---------------------------------------------------------------------------
__device__ __forceinline__ float ftf32(float f) {
    uint32_t u;
    asm("cvt.rna.tf32.f32 %0, %1;" : "=r"(u) : "f"(f));
    return __uint_as_float(u);
}

__device__ __forceinline__ void cpa16(void* dst_smem, const void* src_gmem) {
    uint32_t d = (uint32_t)__cvta_generic_to_shared(dst_smem);
    asm volatile("cp.async.cg.shared.global [%0], [%1], 16;\n" :: "r"(d), "l"(src_gmem));
}

// ---------------------------------------------------------------------------
// 1) tf32 pre-rounding (round-to-nearest, unbiased)
// ---------------------------------------------------------------------------
__global__ void round_x_kernel(const float* __restrict__ x) {
    size_t i = (size_t)blockIdx.x * blockDim.x + threadIdx.x;
    float4 v = reinterpret_cast<const float4*>(x)[i];
    v.x = ftf32(v.x); v.y = ftf32(v.y); v.z = ftf32(v.z); v.w = ftf32(v.w);
    reinterpret_cast<float4*>(d_xr)[i] = v;
}
__global__ void round_w_kernel(const float* __restrict__ w) {
    size_t i = (size_t)blockIdx.x * blockDim.x + threadIdx.x;
    float4 v = reinterpret_cast<const float4*>(w)[i];
    v.x = ftf32(v.x); v.y = ftf32(v.y); v.z = ftf32(v.z); v.w = ftf32(v.w);
    reinterpret_cast<float4*>(d_wr)[i] = v;
}

// ---------------------------------------------------------------------------
// 2) gate: one warp per sample
// ---------------------------------------------------------------------------
__global__ void gate_kernel(const float* __restrict__ x,
                            const float* __restrict__ wg,
                            const float* __restrict__ wgb,
                            float* __restrict__ Gout) {
    int warp = (blockIdx.x * blockDim.x + threadIdx.x) >> 5;
    int lane = threadIdx.x & 31;
    if (warp >= BSZ) return;
    const float* xr = x + (size_t)warp * DK;
    float s = 0.f;
    #pragma unroll 8
    for (int i = lane; i < DK; i += 32) s = fmaf(xr[i], wg[i], s);
    #pragma unroll
    for (int o = 16; o; o >>= 1) s += __shfl_xor_sync(0xffffffffu, s, o);
    float g = 4.0f * (1.0f + tanhf(s + wgb[0]));
    int k = (int)floorf(g);
    if (k < 0) k = 0;
    if (k > NCOMP) k = NCOMP;          // k in [0, 8]
    int cnt = k + 1; if (cnt > NCOMP) cnt = NCOMP;
    float inv = 1.0f / (float)cnt;
    if (lane == 0) { d_ginv[warp] = inv; d_gk[warp] = k; }
    if (Gout != nullptr && lane < NCOMP)
        Gout[(size_t)warp * NCOMP + lane] = (lane <= k) ? inv : 0.0f;
}

// ---------------------------------------------------------------------------
// 2b) deterministic counting sort of rows by k descending (single CTA)
// ---------------------------------------------------------------------------
#define SORT_T 256
#define PER_T (BSZ / SORT_T)   // 16
__global__ void sort_kernel() {
    __shared__ int tcnt[SORT_T][NCOMP + 1];
    const int t = threadIdx.x;
    int lc[NCOMP + 1];
    #pragma unroll
    for (int b = 0; b <= NCOMP; b++) lc[b] = 0;
    #pragma unroll
    for (int i = 0; i < PER_T; i++) lc[d_gk[t * PER_T + i]]++;
    #pragma unroll
    for (int b = 0; b <= NCOMP; b++) tcnt[t][b] = lc[b];
    __syncthreads();
    if (t == 0) {
        int run = 0;
        for (int b = NCOMP; b >= 0; b--) {          // descending k
            for (int th = 0; th < SORT_T; th++) {
                int c = tcnt[th][b];
                tcnt[th][b] = run;
                run += c;
            }
            d_cnt_ge[b] = run;                       // #rows with k >= b
        }
    }
    __syncthreads();
    int off[NCOMP + 1];
    #pragma unroll
    for (int b = 0; b <= NCOMP; b++) off[b] = tcnt[t][b];
    #pragma unroll
    for (int i = 0; i < PER_T; i++) {
        int row = t * PER_T + i;
        int b = d_gk[row];
        d_perm[off[b]++] = row;
    }
}

// ---------------------------------------------------------------------------
// 2c) zero-fill the gated-off output cells (n > k[b])
// ---------------------------------------------------------------------------
__global__ void zfill_kernel(float* __restrict__ out) {
    const int b = blockIdx.x;
    int k = d_gk[b]; if (k > NCOMP - 1) k = NCOMP - 1;
    const int start = (k + 1) * (CCH / 4);           // in float4 units
    float4* p = reinterpret_cast<float4*>(out + (size_t)b * NOUT);
    const float4 z = make_float4(0.f, 0.f, 0.f, 0.f);
    for (int i = start + threadIdx.x; i < NOUT / 4; i += blockDim.x) p[i] = z;
}

// ---------------------------------------------------------------------------
// 3) gathered GEMM: for component comp, rows = perm[0 : cnt_ge[comp]]
//    out[gr, comp*1024 + c] = (x[gr,:].W[col,:] + bias[col]) * inv[gr]
// ---------------------------------------------------------------------------
__global__ __launch_bounds__(GEMM_THREADS, 1)
void gemm_kernel(const float* __restrict__ bias, float* __restrict__ out) {
    extern __shared__ char smemraw[];
    int*   sperm = reinterpret_cast<int*>(smemraw);
    float* smem  = reinterpret_cast<float*>(smemraw + SPERM_BYTES);

    const int comp   = blockIdx.x >> 2;         // 0..7
    const int ntile  = blockIdx.x & 3;          // 0..3
    const int mtile  = blockIdx.y;               // 0..31
    const int rows   = d_cnt_ge[comp];
    if (mtile * BM >= rows) return;              // uniform early exit
    const int nvalid = min(BM, rows - mtile * BM);
    const int colBase = comp * CCH + ntile * BN;

    const int tid  = threadIdx.x;
    const int lane = tid & 31;
    const int warp = tid >> 5;
    const int wm   = warp >> 2;            // 0..1  (64 rows each)
    const int wn   = warp & 3;             // 0..3  (64 cols each)
    const int lr = lane >> 2;              // 0..7
    const int lc = lane & 3;               // 0..3

    // stage perm slice (clamped for partial tiles)
    if (tid < BM) {
        int idx = mtile * BM + min(tid, nvalid - 1);
        sperm[tid] = d_perm[idx];
    }
    __syncthreads();

    // per-thread gathered A source pointers (fixed rows across all k-tiles)
    const int arow = tid >> 3;             // 0..31
    const int ach  = tid & 7;              // 16B chunk
    const float* aptr[4];
    #pragma unroll
    for (int i = 0; i < 4; i++)
        aptr[i] = d_xr + (size_t)sperm[arow + i * 32] * DK + ach * 4;
    const float* bptr[8];
    #pragma unroll
    for (int i = 0; i < 8; i++)
        bptr[i] = d_wr + (size_t)(colBase + arow + i * 32) * DK + ach * 4;

    float c[4][8][4];
    #pragma unroll
    for (int i = 0; i < 4; i++)
        #pragma unroll
        for (int j = 0; j < 8; j++)
            #pragma unroll
            for (int r = 0; r < 4; r++) c[i][j][r] = 0.f;

    auto loadStage = [&](int s, int kt) {
        const int k0 = kt * BK;
        float* As = smem + (size_t)s * STAGE_FLOATS;
        float* Bs = As + A_FLOATS;
        #pragma unroll
        for (int i = 0; i < 4; i++)
            cpa16(&As[(arow + i * 32) * LDSD + ach * 4], aptr[i] + k0);
        #pragma unroll
        for (int i = 0; i < 8; i++)
            cpa16(&Bs[(arow + i * 32) * LDSD + ach * 4], bptr[i] + k0);
        asm volatile("cp.async.commit_group;\n" ::);
    };

    auto computeStage = [&](int s) {
        const float* as = smem + (size_t)s * STAGE_FLOATS;
        const float* bs = as + A_FLOATS;
        #pragma unroll
        for (int ks = 0; ks < BK / 8; ks++) {
            const int kc = ks * 8 + lc;
            uint32_t a[4][4], b[8][2];
            #pragma unroll
            for (int i = 0; i < 4; i++) {
                int r0 = wm * 64 + i * 16;
                a[i][0] = __float_as_uint(as[(r0 + lr)     * LDSD + kc]);
                a[i][1] = __float_as_uint(as[(r0 + lr + 8) * LDSD + kc]);
                a[i][2] = __float_as_uint(as[(r0 + lr)     * LDSD + kc + 4]);
                a[i][3] = __float_as_uint(as[(r0 + lr + 8) * LDSD + kc + 4]);
            }
            #pragma unroll
            for (int j = 0; j < 8; j++) {
                int n0 = wn * 64 + j * 8;
                b[j][0] = __float_as_uint(bs[(n0 + lr) * LDSD + kc]);
                b[j][1] = __float_as_uint(bs[(n0 + lr) * LDSD + kc + 4]);
            }
            #pragma unroll
            for (int i = 0; i < 4; i++)
                #pragma unroll
                for (int j = 0; j < 8; j++)
                    asm volatile(
                        "mma.sync.aligned.m16n8k8.row.col.f32.tf32.tf32.f32 "
                        "{%0,%1,%2,%3},{%4,%5,%6,%7},{%8,%9},{%0,%1,%2,%3};\n"
                        : "+f"(c[i][j][0]), "+f"(c[i][j][1]),
                          "+f"(c[i][j][2]), "+f"(c[i][j][3])
                        : "r"(a[i][0]), "r"(a[i][1]), "r"(a[i][2]), "r"(a[i][3]),
                          "r"(b[j][0]), "r"(b[j][1]));
        }
    };

    loadStage(0, 0);
    loadStage(1, 1);

    #pragma unroll 1
    for (int kt = 0; kt < KT; kt++) {
        asm volatile("cp.async.wait_group %0;\n" :: "n"(NSTAGE - 2));
        __syncthreads();
        if (kt + NSTAGE - 1 < KT)
            loadStage((kt + NSTAGE - 1) % NSTAGE, kt + NSTAGE - 1);
        computeStage(kt % NSTAGE);
    }

    // ---------------- epilogue: bias + per-row scale, scatter rows ----------
    #pragma unroll
    for (int i = 0; i < 4; i++) {
        #pragma unroll
        for (int h = 0; h < 2; h++) {
            const int rloc = wm * 64 + i * 16 + lr + h * 8;
            if (rloc >= nvalid) continue;
            const int gr = sperm[rloc];
            const float sc = d_ginv[gr];           // comp <= k[gr] by construction
            #pragma unroll
            for (int j = 0; j < 8; j++) {
                const int cb = colBase + wn * 64 + j * 8 + lc * 2;
                const float2 bb = *reinterpret_cast<const float2*>(&bias[cb]);
                float2 v;
                v.x = (c[i][j][2 * h + 0] + bb.x) * sc;
                v.y = (c[i][j][2 * h + 1] + bb.y) * sc;
                *reinterpret_cast<float2*>(&out[(size_t)gr * NOUT + cb]) = v;
            }
        }
    }
}

// ---------------------------------------------------------------------------
extern "C" void kernel_launch(void* const* d_in, const int* in_sizes, int n_in,
                              void* d_out, int out_size) {
    const float* x    = (const float*)d_in[0];
    const float* W    = (const float*)d_in[1];
    const float* bias = (const float*)d_in[2];
    const float* wg   = (const float*)d_in[3];
    const float* wgb  = (const float*)d_in[4];
    float* out = (float*)d_out;

    // output layout: E [BSZ*NOUT] then G [BSZ*NCOMP]
    float* Gout = nullptr;
    if ((size_t)out_size >= (size_t)BSZ * NOUT + (size_t)BSZ * NCOMP)
        Gout = out + (size_t)BSZ * NOUT;

    cudaFuncSetAttribute(gemm_kernel, cudaFuncAttributeMaxDynamicSharedMemorySize,
                         SMEM_BYTES);

    // 1) tf32 pre-rounding
    round_x_kernel<<<(BSZ * (DK / 4)) / 256, 256>>>(x);
    round_w_kernel<<<((size_t)NOUT * (DK / 4)) / 256, 256>>>(W);

    // 2) gate -> sort rows by k desc -> zero-fill dead outputs
    gate_kernel<<<(BSZ * 32) / 256, 256>>>(x, wg, wgb, Gout);
    sort_kernel<<<1, SORT_T>>>();
    zfill_kernel<<<BSZ, 128>>>(out);

    // 3) gathered GEMM over live (row, component) pairs only
    dim3 grid(NCOMP * 4, BSZ / BM);   // (comp x ntile) x mtile, early-exit
    gemm_kernel<<<grid, GEMM_THREADS, SMEM_BYTES>>>(bias, out);
}

// round 5
// speedup vs baseline: 2.8256x; 1.8063x over previous
#include <cuda_runtime.h>
#include <cuda_fp16.h>
#include <cstdint>

// ---------------------------------------------------------------------------
// Problem constants
// ---------------------------------------------------------------------------
#define BSZ   4096          // batch (GEMM M)
#define DK    2048          // in_features (GEMM K)
#define NCOMP 8
#define CCH   1024
#define NOUT  8192          // GEMM N

// ---------------------------------------------------------------------------
// GEMM tiling: CTA 128x256, warp tile 64x64 (2x4), BK=64 halves, 3 stages
// ---------------------------------------------------------------------------
#define BM 128
#define BN 256
#define BK 64                     // k-elements per stage (128B rows in fp16)
#define KT (DK / BK)              // 32
#define NSTAGE 3
#define LDSD_H 72                 // padded half stride (144B, 16B-aligned)
#define A_HALFS (BM * LDSD_H)     // 9216
#define B_HALFS (BN * LDSD_H)     // 18432
#define STAGE_HALFS (A_HALFS + B_HALFS)             // 27648
#define SPERM_BYTES 512
#define SMEM_BYTES (SPERM_BYTES + NSTAGE * STAGE_HALFS * 2)   // 166400
#define GEMM_THREADS 256

// ---------------------------------------------------------------------------
// Scratch (static device arrays; no allocations)
// ---------------------------------------------------------------------------
__device__ __align__(1024) __half d_xh[(size_t)BSZ * DK];     // 16 MB fp16 x
__device__ __align__(1024) __half d_wh[(size_t)NOUT * DK];    // 32 MB fp16 W
__device__ float d_ginv[BSZ];
__device__ int   d_gk[BSZ];
__device__ int   d_perm[BSZ];         // rows sorted by k descending
__device__ int   d_cnt_ge[NCOMP + 1]; // cnt_ge[n] = #rows with k >= n

// ---------------------------------------------------------------------------
// helpers
// ---------------------------------------------------------------------------
__device__ __forceinline__ void cpa16(void* dst_smem, const void* src_gmem) {
    uint32_t d = (uint32_t)__cvta_generic_to_shared(dst_smem);
    asm volatile("cp.async.cg.shared.global [%0], [%1], 16;\n" :: "r"(d), "l"(src_gmem));
}

// ---------------------------------------------------------------------------
// 1) W conversion f32 -> f16 (rn)
// ---------------------------------------------------------------------------
__global__ void round_w_kernel(const float* __restrict__ w) {
    size_t i = (size_t)blockIdx.x * blockDim.x + threadIdx.x;   // float4 units
    float4 v = reinterpret_cast<const float4*>(w)[i];
    __half2 h0 = __floats2half2_rn(v.x, v.y);
    __half2 h1 = __floats2half2_rn(v.z, v.w);
    uint2 o;
    o.x = *reinterpret_cast<uint32_t*>(&h0);
    o.y = *reinterpret_cast<uint32_t*>(&h1);
    reinterpret_cast<uint2*>(d_xh + 0)[0] = o;   // placeholder (overwritten below)
}

// (real one — separate to avoid the accidental placeholder above)
__global__ void conv_w_kernel(const float* __restrict__ w) {
    size_t i = (size_t)blockIdx.x * blockDim.x + threadIdx.x;   // float4 units
    float4 v = reinterpret_cast<const float4*>(w)[i];
    __half2 h0 = __floats2half2_rn(v.x, v.y);
    __half2 h1 = __floats2half2_rn(v.z, v.w);
    uint2 o;
    o.x = *reinterpret_cast<uint32_t*>(&h0);
    o.y = *reinterpret_cast<uint32_t*>(&h1);
    reinterpret_cast<uint2*>(d_wh)[i] = o;
}

// ---------------------------------------------------------------------------
// 2) gate + x conversion fused: one warp per sample.
//    reads x row once; writes fp16 row + gate results.
// ---------------------------------------------------------------------------
__global__ void gate_kernel(const float* __restrict__ x,
                            const float* __restrict__ wg,
                            const float* __restrict__ wgb,
                            float* __restrict__ Gout) {
    int warp = (blockIdx.x * blockDim.x + threadIdx.x) >> 5;
    int lane = threadIdx.x & 31;
    if (warp >= BSZ) return;
    const float4* xr = reinterpret_cast<const float4*>(x + (size_t)warp * DK);
    const float4* wr = reinterpret_cast<const float4*>(wg);
    uint2* xo = reinterpret_cast<uint2*>(d_xh + (size_t)warp * DK);
    float s = 0.f;
    #pragma unroll
    for (int j = 0; j < DK / 4 / 32; j++) {            // 16 chunks per lane
        int c = j * 32 + lane;
        float4 v = xr[c];
        float4 g = wr[c];
        s = fmaf(v.x, g.x, s); s = fmaf(v.y, g.y, s);
        s = fmaf(v.z, g.z, s); s = fmaf(v.w, g.w, s);
        __half2 h0 = __floats2half2_rn(v.x, v.y);
        __half2 h1 = __floats2half2_rn(v.z, v.w);
        uint2 o;
        o.x = *reinterpret_cast<uint32_t*>(&h0);
        o.y = *reinterpret_cast<uint32_t*>(&h1);
        xo[c] = o;
    }
    #pragma unroll
    for (int o = 16; o; o >>= 1) s += __shfl_xor_sync(0xffffffffu, s, o);
    float g = 4.0f * (1.0f + tanhf(s + wgb[0]));
    int k = (int)floorf(g);
    if (k < 0) k = 0;
    if (k > NCOMP) k = NCOMP;          // k in [0, 8]
    int cnt = k + 1; if (cnt > NCOMP) cnt = NCOMP;
    float inv = 1.0f / (float)cnt;
    if (lane == 0) { d_ginv[warp] = inv; d_gk[warp] = k; }
    if (Gout != nullptr && lane < NCOMP)
        Gout[(size_t)warp * NCOMP + lane] = (lane <= k) ? inv : 0.0f;
}

// ---------------------------------------------------------------------------
// 2b) counting sort by k descending — warp-scan parallel, single CTA
// ---------------------------------------------------------------------------
#define SORT_T 256
#define PER_T (BSZ / SORT_T)   // 16
__global__ void sort_kernel() {
    __shared__ int wpart[NCOMP + 1][8];   // per-warp totals per bin
    __shared__ int wbase[NCOMP + 1][8];   // exclusive per-warp offsets
    __shared__ int tot[NCOMP + 1];
    __shared__ int sbase[NCOMP + 1];
    const int t = threadIdx.x, w = t >> 5, lane = t & 31;

    int myk[PER_T];
    int lc[NCOMP + 1];
    #pragma unroll
    for (int b = 0; b <= NCOMP; b++) lc[b] = 0;
    #pragma unroll
    for (int i = 0; i < PER_T; i++) { myk[i] = d_gk[t * PER_T + i]; lc[myk[i]]++; }

    int pre[NCOMP + 1];
    #pragma unroll
    for (int b = 0; b <= NCOMP; b++) {
        int v = lc[b], s = v;
        #pragma unroll
        for (int o = 1; o < 32; o <<= 1) {
            int u = __shfl_up_sync(0xffffffffu, s, o);
            if (lane >= o) s += u;
        }
        pre[b] = s - v;                 // exclusive prefix within warp
        if (lane == 31) wpart[b][w] = s;
    }
    __syncthreads();
    if (t <= NCOMP) {                   // one thread per bin: warp-offset scan
        int run = 0;
        #pragma unroll
        for (int ww = 0; ww < 8; ww++) { wbase[t][ww] = run; run += wpart[t][ww]; }
        tot[t] = run;
    }
    __syncthreads();
    if (t == 0) {                        // descending-bin bases + cnt_ge
        int run = 0;
        for (int b = NCOMP; b >= 0; b--) { sbase[b] = run; run += tot[b]; d_cnt_ge[b] = run; }
    }
    __syncthreads();
    int off[NCOMP + 1];
    #pragma unroll
    for (int b = 0; b <= NCOMP; b++) off[b] = sbase[b] + wbase[b][w] + pre[b];
    #pragma unroll
    for (int i = 0; i < PER_T; i++) {
        int b = myk[i];
        d_perm[off[b]++] = t * PER_T + i;
    }
}

// ---------------------------------------------------------------------------
// 2c) zero-fill the gated-off output cells (n > k[b])
// ---------------------------------------------------------------------------
__global__ void zfill_kernel(float* __restrict__ out) {
    const int b = blockIdx.x;
    int k = d_gk[b]; if (k > NCOMP - 1) k = NCOMP - 1;
    const int start = (k + 1) * (CCH / 4);           // float4 units
    float4* p = reinterpret_cast<float4*>(out + (size_t)b * NOUT);
    const float4 z = make_float4(0.f, 0.f, 0.f, 0.f);
    for (int i = start + threadIdx.x; i < NOUT / 4; i += blockDim.x) p[i] = z;
}

// ---------------------------------------------------------------------------
// 3) gathered fp16 GEMM: component comp uses rows perm[0 : cnt_ge[comp]]
//    mma.sync m16n8k16.f16 (2x MACs/instr vs tf32 k8)
// ---------------------------------------------------------------------------
__global__ __launch_bounds__(GEMM_THREADS, 1)
void gemm_kernel(const float* __restrict__ bias, float* __restrict__ out) {
    extern __shared__ char smemraw[];
    int*    sperm = reinterpret_cast<int*>(smemraw);
    __half* smem  = reinterpret_cast<__half*>(smemraw + SPERM_BYTES);

    const int comp   = blockIdx.x >> 2;          // 0..7
    const int ntile  = blockIdx.x & 3;           // 0..3
    const int mtile  = blockIdx.y;                // 0..31
    const int rows   = d_cnt_ge[comp];
    if (mtile * BM >= rows) return;               // uniform early exit
    const int nvalid = min(BM, rows - mtile * BM);
    const int colBase = comp * CCH + ntile * BN;

    const int tid  = threadIdx.x;
    const int lane = tid & 31;
    const int warp = tid >> 5;
    const int wm   = warp >> 2;             // 0..1  (64 rows each)
    const int wn   = warp & 3;              // 0..3  (64 cols each)
    const int lr = lane >> 2;               // 0..7
    const int lc = lane & 3;                // 0..3

    if (tid < BM) {
        int idx = mtile * BM + min(tid, nvalid - 1);
        sperm[tid] = d_perm[idx];
    }
    __syncthreads();

    // gathered source pointers (fixed rows across k-tiles)
    const int arow = tid >> 3;              // 0..31
    const int ach  = tid & 7;               // 16B chunk (8 halves)
    const __half* aptr[4];
    #pragma unroll
    for (int i = 0; i < 4; i++)
        aptr[i] = d_xh + (size_t)sperm[arow + i * 32] * DK + ach * 8;
    const __half* bptr[8];
    #pragma unroll
    for (int i = 0; i < 8; i++)
        bptr[i] = d_wh + (size_t)(colBase + arow + i * 32) * DK + ach * 8;

    float c[4][8][4];
    #pragma unroll
    for (int i = 0; i < 4; i++)
        #pragma unroll
        for (int j = 0; j < 8; j++)
            #pragma unroll
            for (int r = 0; r < 4; r++) c[i][j][r] = 0.f;

    auto loadStage = [&](int s, int kt) {
        const int k0 = kt * BK;
        __half* As = smem + (size_t)s * STAGE_HALFS;
        __half* Bs = As + A_HALFS;
        #pragma unroll
        for (int i = 0; i < 4; i++)
            cpa16(&As[(arow + i * 32) * LDSD_H + ach * 8], aptr[i] + k0);
        #pragma unroll
        for (int i = 0; i < 8; i++)
            cpa16(&Bs[(arow + i * 32) * LDSD_H + ach * 8], bptr[i] + k0);
        asm volatile("cp.async.commit_group;\n" ::);
    };

    auto computeStage = [&](int s) {
        const __half* as = smem + (size_t)s * STAGE_HALFS;
        const __half* bs = as + A_HALFS;
        #pragma unroll
        for (int ks = 0; ks < BK / 16; ks++) {   // 4 steps of k16
            const int kc = ks * 16 + 2 * lc;
            uint32_t a[4][4], b[8][2];
            #pragma unroll
            for (int i = 0; i < 4; i++) {
                int r0 = wm * 64 + i * 16;
                a[i][0] = *reinterpret_cast<const uint32_t*>(&as[(r0 + lr)     * LDSD_H + kc]);
                a[i][1] = *reinterpret_cast<const uint32_t*>(&as[(r0 + lr + 8) * LDSD_H + kc]);
                a[i][2] = *reinterpret_cast<const uint32_t*>(&as[(r0 + lr)     * LDSD_H + kc + 8]);
                a[i][3] = *reinterpret_cast<const uint32_t*>(&as[(r0 + lr + 8) * LDSD_H + kc + 8]);
            }
            #pragma unroll
            for (int j = 0; j < 8; j++) {
                int n0 = wn * 64 + j * 8;
                b[j][0] = *reinterpret_cast<const uint32_t*>(&bs[(n0 + lr) * LDSD_H + kc]);
                b[j][1] = *reinterpret_cast<const uint32_t*>(&bs[(n0 + lr) * LDSD_H + kc + 8]);
            }
            #pragma unroll
            for (int i = 0; i < 4; i++)
                #pragma unroll
                for (int j = 0; j < 8; j++)
                    asm volatile(
                        "mma.sync.aligned.m16n8k16.row.col.f32.f16.f16.f32 "
                        "{%0,%1,%2,%3},{%4,%5,%6,%7},{%8,%9},{%0,%1,%2,%3};\n"
                        : "+f"(c[i][j][0]), "+f"(c[i][j][1]),
                          "+f"(c[i][j][2]), "+f"(c[i][j][3])
                        : "r"(a[i][0]), "r"(a[i][1]), "r"(a[i][2]), "r"(a[i][3]),
                          "r"(b[j][0]), "r"(b[j][1]));
        }
    };

    loadStage(0, 0);
    loadStage(1, 1);

    #pragma unroll 1
    for (int kt = 0; kt < KT; kt++) {
        asm volatile("cp.async.wait_group %0;\n" :: "n"(NSTAGE - 2));
        __syncthreads();
        if (kt + NSTAGE - 1 < KT)
            loadStage((kt + NSTAGE - 1) % NSTAGE, kt + NSTAGE - 1);
        computeStage(kt % NSTAGE);
    }

    // ---------------- epilogue: bias + per-row scale, scatter rows ----------
    #pragma unroll
    for (int i = 0; i < 4; i++) {
        #pragma unroll
        for (int h = 0; h < 2; h++) {
            const int rloc = wm * 64 + i * 16 + lr + h * 8;
            if (rloc >= nvalid) continue;
            const int gr = sperm[rloc];
            const float sc = d_ginv[gr];            // comp <= k[gr] by construction
            #pragma unroll
            for (int j = 0; j < 8; j++) {
                const int cb = colBase + wn * 64 + j * 8 + lc * 2;
                const float2 bb = *reinterpret_cast<const float2*>(&bias[cb]);
                float2 v;
                v.x = (c[i][j][2 * h + 0] + bb.x) * sc;
                v.y = (c[i][j][2 * h + 1] + bb.y) * sc;
                *reinterpret_cast<float2*>(&out[(size_t)gr * NOUT + cb]) = v;
            }
        }
    }
}

// ---------------------------------------------------------------------------
extern "C" void kernel_launch(void* const* d_in, const int* in_sizes, int n_in,
                              void* d_out, int out_size) {
    const float* x    = (const float*)d_in[0];
    const float* W    = (const float*)d_in[1];
    const float* bias = (const float*)d_in[2];
    const float* wg   = (const float*)d_in[3];
    const float* wgb  = (const float*)d_in[4];
    float* out = (float*)d_out;

    // output layout: E [BSZ*NOUT] then G [BSZ*NCOMP]
    float* Gout = nullptr;
    if ((size_t)out_size >= (size_t)BSZ * NOUT + (size_t)BSZ * NCOMP)
        Gout = out + (size_t)BSZ * NOUT;

    cudaFuncSetAttribute(gemm_kernel, cudaFuncAttributeMaxDynamicSharedMemorySize,
                         SMEM_BYTES);

    // 1) W f32 -> f16
    conv_w_kernel<<<((size_t)NOUT * (DK / 4)) / 256, 256>>>(W);
    // 2) gate + fused x conversion, then sort + zero-fill
    gate_kernel<<<(BSZ * 32) / 256, 256>>>(x, wg, wgb, Gout);
    sort_kernel<<<1, SORT_T>>>();
    zfill_kernel<<<BSZ, 128>>>(out);
    // 3) gathered fp16 GEMM over live (row, component) pairs
    dim3 grid(NCOMP * 4, BSZ / BM);   // (comp x ntile) x mtile, early-exit
    gemm_kernel<<<grid, GEMM_THREADS, SMEM_BYTES>>>(bias, out);
}